// round 1
// baseline (speedup 1.0000x reference)
#include <cuda_runtime.h>
#include <math_constants.h>

#define BB 16
#define KK 256
#define ZZ 128
#define HH 128
#define BK (BB*KK)
#define L_ROWS 16

// scratch (allocation-free: __device__ globals)
__device__ float g_m1[BK*ZZ];
__device__ float g_m2[BK*ZZ];
__device__ float g_mm[BK*ZZ];

// ---------------------------------------------------------------------------
// Kernel 1: y = x @ W^T + b for both (W1,b1)->g_m1 and (W2,b2)->g_m2
// grid = (BK/L_ROWS, 2), block = 128 (thread = output channel z)
// ---------------------------------------------------------------------------
__global__ __launch_bounds__(128) void lin_kernel(
    const float* __restrict__ z,
    const float* __restrict__ W1, const float* __restrict__ b1,
    const float* __restrict__ W2, const float* __restrict__ b2) {
  const float* W    = blockIdx.y ? W2 : W1;
  const float* bias = blockIdx.y ? b2 : b1;
  float*       y    = blockIdx.y ? g_m2 : g_m1;

  const int row0 = blockIdx.x * L_ROWS;
  const int t = threadIdx.x;

  __shared__ float xs[L_ROWS][ZZ];
#pragma unroll
  for (int r = 0; r < L_ROWS; r++) xs[r][t] = z[(row0 + r) * ZZ + t];
  __syncthreads();

  float acc[L_ROWS];
  const float bz = bias[t];
#pragma unroll
  for (int r = 0; r < L_ROWS; r++) acc[r] = bz;

  const float4* Wr = (const float4*)(W + t * ZZ);
#pragma unroll 8
  for (int c4 = 0; c4 < ZZ / 4; c4++) {
    const float4 w = Wr[c4];
#pragma unroll
    for (int r = 0; r < L_ROWS; r++) {
      const float4 xv = *(const float4*)(&xs[r][c4 * 4]);
      acc[r] = fmaf(w.x, xv.x, acc[r]);
      acc[r] = fmaf(w.y, xv.y, acc[r]);
      acc[r] = fmaf(w.z, xv.z, acc[r]);
      acc[r] = fmaf(w.w, xv.w, acc[r]);
    }
  }
#pragma unroll
  for (int r = 0; r < L_ROWS; r++) y[(row0 + r) * ZZ + t] = acc[r];
}

// ---------------------------------------------------------------------------
// Kernel 2: masked neighbor max + relu(m1 + max) -> g_mm
// grid = (K/16, B), block = 512 (16 warps, warp = one destination node i)
// smem: full m2z[b] tile, 256x128 fp32 = 128 KB (dynamic)
// Iterates only SET bits of the adjacency column via warp-uniform ballot words.
// ---------------------------------------------------------------------------
extern __shared__ float s_m2[];

__global__ __launch_bounds__(512) void maxagg_kernel(const int* __restrict__ P) {
  const int b   = blockIdx.y;
  const int tid = threadIdx.x;

  // stage m2z[b] into smem (coalesced float4)
  {
    float4*       s4 = (float4*)s_m2;
    const float4* g4 = (const float4*)(g_m2 + b * KK * ZZ);
    for (int idx = tid; idx < KK * ZZ / 4; idx += 512) s4[idx] = g4[idx];
  }
  __syncthreads();

  const int warp = tid >> 5;
  const int lane = tid & 31;
  const int i    = blockIdx.x * 16 + warp;

  // build 8x32-bit warp-uniform neighbor masks: bit j set iff P[b,j,i] != 0
  unsigned words[8];
  const int* Pb = P + b * KK * KK;
#pragma unroll
  for (int wd = 0; wd < 8; wd++) {
    const int pv = Pb[(wd * 32 + lane) * KK + i];
    words[wd] = __ballot_sync(0xFFFFFFFFu, pv != 0);
  }

  float4 acc = make_float4(-CUDART_INF_F, -CUDART_INF_F, -CUDART_INF_F, -CUDART_INF_F);
  const float4* sm = (const float4*)s_m2;  // [256][32] float4, lane -> z chunk

#pragma unroll
  for (int wd = 0; wd < 8; wd++) {
    unsigned word = words[wd];
    const int base = wd * 32;
    while (word) {  // warp-uniform loop: only active neighbors
      const int j = base + __ffs((int)word) - 1;
      word &= word - 1;
      const float4 v = sm[j * (ZZ / 4) + lane];
      acc.x = fmaxf(acc.x, v.x);
      acc.y = fmaxf(acc.y, v.y);
      acc.z = fmaxf(acc.z, v.z);
      acc.w = fmaxf(acc.w, v.w);
    }
  }

  const int ri = (b * KK + i) * ZZ + lane * 4;
  const float4 m1 = *(const float4*)(g_m1 + ri);
  float4 o;
  o.x = fmaxf(m1.x + acc.x, 0.0f);
  o.y = fmaxf(m1.y + acc.y, 0.0f);
  o.z = fmaxf(m1.z + acc.z, 0.0f);
  o.w = fmaxf(m1.w + acc.w, 0.0f);
  *(float4*)(g_mm + ri) = o;
}

// ---------------------------------------------------------------------------
// Kernel 3: out = relu([z, m] @ Wu^T + bu)
// grid = BK/L_ROWS, block = 128 (thread = output head h)
// ---------------------------------------------------------------------------
__global__ __launch_bounds__(128) void out_kernel(
    const float* __restrict__ z,
    const float* __restrict__ Wu, const float* __restrict__ bu,
    float* __restrict__ out) {
  const int row0 = blockIdx.x * L_ROWS;
  const int t = threadIdx.x;

  __shared__ float xs[L_ROWS][2 * ZZ];
#pragma unroll
  for (int r = 0; r < L_ROWS; r++) {
    xs[r][t]      = z[(row0 + r) * ZZ + t];
    xs[r][ZZ + t] = g_mm[(row0 + r) * ZZ + t];
  }
  __syncthreads();

  float acc[L_ROWS];
  const float bz = bu[t];
#pragma unroll
  for (int r = 0; r < L_ROWS; r++) acc[r] = bz;

  const float4* Wr = (const float4*)(Wu + t * 2 * ZZ);
#pragma unroll 8
  for (int c4 = 0; c4 < 2 * ZZ / 4; c4++) {
    const float4 w = Wr[c4];
#pragma unroll
    for (int r = 0; r < L_ROWS; r++) {
      const float4 xv = *(const float4*)(&xs[r][c4 * 4]);
      acc[r] = fmaf(w.x, xv.x, acc[r]);
      acc[r] = fmaf(w.y, xv.y, acc[r]);
      acc[r] = fmaf(w.z, xv.z, acc[r]);
      acc[r] = fmaf(w.w, xv.w, acc[r]);
    }
  }
#pragma unroll
  for (int r = 0; r < L_ROWS; r++)
    out[(row0 + r) * HH + t] = fmaxf(acc[r], 0.0f);
}

// ---------------------------------------------------------------------------
extern "C" void kernel_launch(void* const* d_in, const int* in_sizes, int n_in,
                              void* d_out, int out_size) {
  const float* z  = (const float*)d_in[0];
  const int*   P  = (const int*)  d_in[1];
  const float* W1 = (const float*)d_in[2];
  const float* b1 = (const float*)d_in[3];
  const float* W2 = (const float*)d_in[4];
  const float* b2 = (const float*)d_in[5];
  const float* Wu = (const float*)d_in[6];
  const float* bu = (const float*)d_in[7];
  float* out = (float*)d_out;

  static bool attr_set = false;
  // idempotent, deterministic, not a stream op — safe under capture
  cudaFuncSetAttribute(maxagg_kernel, cudaFuncAttributeMaxDynamicSharedMemorySize,
                       KK * ZZ * (int)sizeof(float));
  (void)attr_set;

  lin_kernel<<<dim3(BK / L_ROWS, 2), 128>>>(z, W1, b1, W2, b2);
  maxagg_kernel<<<dim3(KK / 16, BB), 512, KK * ZZ * sizeof(float)>>>(P);
  out_kernel<<<BK / L_ROWS, 128>>>(z, Wu, bu, out);
}